// round 13
// baseline (speedup 1.0000x reference)
#include <cuda_runtime.h>
#include <cuda_fp16.h>
#include <math.h>
#include <stdint.h>

#define LQ  4096
#define DD  2048
#define TT  4096
#define WIN 1024

// ---------------- scratch (device globals; no allocation APIs) --------------
__device__ alignas(16) __half g_w16[(size_t)DD * DD];   // Wq fp16
__device__ alignas(16) __half g_q16[(size_t)LQ * DD];   // Q*scale fp16
__device__ alignas(16) __half g_v16[(size_t)DD * TT];   // Pv^T fp16
__device__ float g_S [(size_t)LQ * TT];                 // scores fp32 (band)
__device__ float g_pm[(size_t)LQ * 32];                 // per-(row,tile) max
__device__ float g_pl[(size_t)LQ * 32];                 // per-(row,tile) sumexp
__device__ float g_rowM[LQ];                            // row max
__device__ float g_rowI[LQ];                            // 1 / row sumexp

// ---------------- PTX helpers ----------------------------------------------
__device__ __forceinline__ uint32_t smem_u32(const void* p) {
    uint32_t a;
    asm("{ .reg .u64 t; cvta.to.shared.u64 t, %1; cvt.u32.u64 %0, t; }"
        : "=r"(a) : "l"(p));
    return a;
}
#define CP_ASYNC16(dst, src) \
    asm volatile("cp.async.cg.shared.global [%0], [%1], 16;" :: "r"(dst), "l"(src))
#define CP_COMMIT() asm volatile("cp.async.commit_group;" ::: "memory")
#define CP_WAIT(n)  asm volatile("cp.async.wait_group %0;" :: "n"(n) : "memory")

#define LDSM4(r0, r1, r2, r3, addr) \
    asm volatile("ldmatrix.sync.aligned.m8n8.x4.shared.b16 {%0,%1,%2,%3}, [%4];" \
                 : "=r"(r0), "=r"(r1), "=r"(r2), "=r"(r3) : "r"(addr))

__device__ __forceinline__ void mma_f16(float* c, const uint32_t* a, const uint32_t* b) {
    asm volatile("mma.sync.aligned.m16n8k16.row.col.f32.f16.f16.f32 "
                 "{%0,%1,%2,%3}, {%4,%5,%6,%7}, {%8,%9}, {%0,%1,%2,%3};"
                 : "+f"(c[0]), "+f"(c[1]), "+f"(c[2]), "+f"(c[3])
                 : "r"(a[0]), "r"(a[1]), "r"(a[2]), "r"(a[3]),
                   "r"(b[0]), "r"(b[1]));
}

// ---------------- fused fp16 NT GEMM ----------------------------------------
// C[M,N] = A[M,K] * B[N,K]^T. 128x128 tile, BK=32, 256 thr, 8 warps of 64x32.
// One operand may be fp32 in gmem (A32/B32): staged raw via cp.async, converted
// to fp16 in smem. EXPA: A conversion applies softmax p = mask?exp(s-M)*I:0.
// PART: epilogue emits masked per-tile row (max, sumexp) partials.
// Direct fp16 operand: 3 smem bufs; raw operand: 2 raw + 2 cvt bufs.
static constexpr int HSTR   = 40;                 // halves per fp16 smem row
static constexpr int TILE_H = 128 * HSTR;         // 5120 halves per tile
static constexpr int RAW_F  = 128 * 36;           // 4608 floats per raw tile
static constexpr int SMEM_B = 5 * TILE_H * 2 + 2 * RAW_F * 4;  // 88064 bytes

template<bool BAND, bool KRANGE, bool A32, bool B32, bool EXPA, bool OUTH, bool PART>
__global__ __launch_bounds__(256, 2)
void h_gemm(const void* __restrict__ Av, const void* __restrict__ Bv,
            float* __restrict__ Cf, __half* __restrict__ Ch,
            float* __restrict__ pm, float* __restrict__ pl,
            const float* __restrict__ rowM, const float* __restrict__ rowI,
            int Ntot, int Ktot, float scale)
{
    const int bm = blockIdx.y, bn = blockIdx.x;
    if (BAND) {
        const int r0 = bm << 7, c0 = bn << 7;
        int dist = 0;
        if (c0 > r0 + 127)      dist = c0 - (r0 + 127);
        else if (r0 > c0 + 127) dist = r0 - (c0 + 127);
        if (dist >= WIN) return;
    }
    int k0 = 0, kend = Ktot;
    if (KRANGE) {
        k0 = 128 * max(0, bm - 8);
        kend = min(Ktot, 128 * (bm + 9));
    }
    const int nT = (kend - k0) >> 5;

    extern __shared__ __half sm[];
    __half* A16 = sm;                                   // A32 ? 2 bufs : 3 bufs
    __half* B16 = sm + (A32 ? 2 : 3) * TILE_H;          // B32 ? 2 bufs : 3 bufs
    float*  RAW = (float*)(sm + 5 * TILE_H);            // 2 bufs

    const int tid = threadIdx.x, lane = tid & 31, w = tid >> 5;
    const int wm = (w & 1) * 64, wn = (w >> 1) * 32;
    const int srow = tid >> 2, sc = tid & 3;            // staging map

    const __half* Ah = (const __half*)Av;
    const __half* Bh = (const __half*)Bv;
    const float*  Afp = (const float*)Av;
    const float*  Bfp = (const float*)Bv;

    // EXPA row constants (rows owned by this thread in staging)
    float M0 = 0.f, I0 = 0.f, M1 = 0.f, I1 = 0.f;
    if (EXPA) {
        M0 = rowM[bm * 128 + srow];      I0 = rowI[bm * 128 + srow];
        M1 = rowM[bm * 128 + srow + 64]; I1 = rowI[bm * 128 + srow + 64];
    }

    auto stage = [&](int s) {
        const int kb = k0 + (s << 5);
        // ---- A ----
        if (A32) {
            float* dst = RAW + (s & 1) * RAW_F;
            #pragma unroll
            for (int h = 0; h < 2; h++) {
                const int r = srow + h * 64;
                const float* src = Afp + (size_t)(bm * 128 + r) * Ktot + kb;
                #pragma unroll
                for (int j = 0; j < 2; j++) {
                    const int c = (sc << 1) + j;
                    CP_ASYNC16(smem_u32(dst + r * 36 + c * 4), src + c * 4);
                }
            }
        } else {
            __half* dst = A16 + (s % 3) * TILE_H;
            #pragma unroll
            for (int h = 0; h < 2; h++) {
                const int r = srow + h * 64;
                CP_ASYNC16(smem_u32(dst + r * HSTR + sc * 8),
                           Ah + (size_t)(bm * 128 + r) * Ktot + kb + sc * 8);
            }
        }
        // ---- B ----
        if (B32) {
            float* dst = RAW + (s & 1) * RAW_F;
            #pragma unroll
            for (int h = 0; h < 2; h++) {
                const int r = srow + h * 64;
                const float* src = Bfp + (size_t)(bn * 128 + r) * Ktot + kb;
                #pragma unroll
                for (int j = 0; j < 2; j++) {
                    const int c = (sc << 1) + j;
                    CP_ASYNC16(smem_u32(dst + r * 36 + c * 4), src + c * 4);
                }
            }
        } else {
            __half* dst = B16 + (s % 3) * TILE_H;
            #pragma unroll
            for (int h = 0; h < 2; h++) {
                const int r = srow + h * 64;
                CP_ASYNC16(smem_u32(dst + r * HSTR + sc * 8),
                           Bh + (size_t)(bn * 128 + r) * Ktot + kb + sc * 8);
            }
        }
    };

    auto convert = [&](int s) {   // raw fp32 -> fp16 tile (A32 or B32)
        const float* rb = RAW + (s & 1) * RAW_F;
        __half* dst = (A32 ? A16 : B16) + (s & 1) * TILE_H;
        const int kb = k0 + (s << 5) + sc * 8;
        #pragma unroll
        for (int h = 0; h < 2; h++) {
            const int row = srow + h * 64;
            float4 v0 = *(const float4*)(rb + row * 36 + sc * 8);
            float4 v1 = *(const float4*)(rb + row * 36 + sc * 8 + 4);
            float p[8] = {v0.x, v0.y, v0.z, v0.w, v1.x, v1.y, v1.z, v1.w};
            if (EXPA) {
                const float M = h ? M1 : M0, I = h ? I1 : I0;
                const int gr = bm * 128 + row;
                #pragma unroll
                for (int j = 0; j < 8; j++) {
                    const int d = gr - (kb + j);
                    p[j] = (d < WIN && d > -WIN) ? __expf(p[j] - M) * I : 0.f;
                }
            }
            __align__(16) __half2 o[4];
            o[0] = __floats2half2_rn(p[0], p[1]);
            o[1] = __floats2half2_rn(p[2], p[3]);
            o[2] = __floats2half2_rn(p[4], p[5]);
            o[3] = __floats2half2_rn(p[6], p[7]);
            *(uint4*)(dst + row * HSTR + sc * 8) = *(uint4*)o;
        }
    };

    float acc[4][4][4] = {};
    const int lr = lane & 7, ls = lane >> 3;

    stage(0); CP_COMMIT();
    if (nT > 1) stage(1);
    CP_COMMIT();
    CP_WAIT(1);
    if (A32 || B32) convert(0);

    for (int t = 0; t < nT; t++) {
        __syncthreads();
        if (t + 2 < nT) stage(t + 2);
        CP_COMMIT();

        const __half* As = A16 + (A32 ? (t & 1) : (t % 3)) * TILE_H;
        const __half* Bs = B16 + (B32 ? (t & 1) : (t % 3)) * TILE_H;

        uint32_t bfr[4][4];
        #pragma unroll
        for (int ni = 0; ni < 4; ni++) {
            uint32_t ad = smem_u32(Bs + (wn + ni * 8 + lr) * HSTR + ls * 8);
            LDSM4(bfr[ni][0], bfr[ni][1], bfr[ni][2], bfr[ni][3], ad);
        }
        #pragma unroll
        for (int ks = 0; ks < 2; ks++) {
            uint32_t af[4][4];
            #pragma unroll
            for (int mi = 0; mi < 4; mi++) {
                uint32_t ad = smem_u32(As + (wm + mi * 16 + lr + (ls & 1) * 8) * HSTR
                                          + ks * 16 + (ls >> 1) * 8);
                LDSM4(af[mi][0], af[mi][1], af[mi][2], af[mi][3], ad);
            }
            #pragma unroll
            for (int mi = 0; mi < 4; mi++)
                #pragma unroll
                for (int ni = 0; ni < 4; ni++)
                    mma_f16(acc[mi][ni], af[mi], &bfr[ni][ks * 2]);
        }
        if (t + 1 < nT) {
            CP_WAIT(1);
            if (A32 || B32) convert(t + 1);
        }
    }

    // ---- main output ----
    #pragma unroll
    for (int mi = 0; mi < 4; mi++) {
        const int row = bm * 128 + wm + mi * 16 + (lane >> 2);
        #pragma unroll
        for (int ni = 0; ni < 4; ni++) {
            const int col = bn * 128 + wn + ni * 8 + 2 * (lane & 3);
            if (OUTH) {
                __half2* p0 = (__half2*)(Ch + (size_t)row * Ntot + col);
                __half2* p1 = (__half2*)(Ch + (size_t)(row + 8) * Ntot + col);
                *p0 = __floats2half2_rn(acc[mi][ni][0] * scale, acc[mi][ni][1] * scale);
                *p1 = __floats2half2_rn(acc[mi][ni][2] * scale, acc[mi][ni][3] * scale);
            } else {
                float2* p0 = (float2*)(Cf + (size_t)row * Ntot + col);
                float2* p1 = (float2*)(Cf + (size_t)(row + 8) * Ntot + col);
                *p0 = make_float2(acc[mi][ni][0] * scale, acc[mi][ni][1] * scale);
                *p1 = make_float2(acc[mi][ni][2] * scale, acc[mi][ni][3] * scale);
            }
        }
    }

    // ---- masked softmax partials (scores GEMM) ----
    if (PART) {
        __syncthreads();                       // smem bufs now reusable
        float* red  = (float*)sm;              // 128 rows x 16 slots
        float* rowm = (float*)sm + 2048;       // 128
        const int slot = ((w >> 1) << 2) + (lane & 3);
        const int rb = wm + (lane >> 2);
        #pragma unroll
        for (int mi = 0; mi < 4; mi++) {
            float m0 = -3.4e38f, m1 = -3.4e38f;
            const int r0g = bm * 128 + rb + mi * 16, r1g = r0g + 8;
            #pragma unroll
            for (int ni = 0; ni < 4; ni++) {
                const int t0 = bn * 128 + wn + ni * 8 + 2 * (lane & 3);
                int d;
                d = r0g - t0;       if (d < WIN && d > -WIN) m0 = fmaxf(m0, acc[mi][ni][0]);
                d = r0g - (t0 + 1); if (d < WIN && d > -WIN) m0 = fmaxf(m0, acc[mi][ni][1]);
                d = r1g - t0;       if (d < WIN && d > -WIN) m1 = fmaxf(m1, acc[mi][ni][2]);
                d = r1g - (t0 + 1); if (d < WIN && d > -WIN) m1 = fmaxf(m1, acc[mi][ni][3]);
            }
            red[(rb + mi * 16) * 16 + slot]       = m0;
            red[(rb + mi * 16 + 8) * 16 + slot]   = m1;
        }
        __syncthreads();
        if (tid < 128) {
            float m = red[tid * 16];
            #pragma unroll
            for (int i = 1; i < 16; i++) m = fmaxf(m, red[tid * 16 + i]);
            rowm[tid] = m;
        }
        __syncthreads();
        #pragma unroll
        for (int mi = 0; mi < 4; mi++) {
            const float Ma = rowm[rb + mi * 16], Mb = rowm[rb + mi * 16 + 8];
            float s0 = 0.f, s1 = 0.f;
            const int r0g = bm * 128 + rb + mi * 16, r1g = r0g + 8;
            #pragma unroll
            for (int ni = 0; ni < 4; ni++) {
                const int t0 = bn * 128 + wn + ni * 8 + 2 * (lane & 3);
                int d;
                d = r0g - t0;       if (d < WIN && d > -WIN) s0 += __expf(acc[mi][ni][0] - Ma);
                d = r0g - (t0 + 1); if (d < WIN && d > -WIN) s0 += __expf(acc[mi][ni][1] - Ma);
                d = r1g - t0;       if (d < WIN && d > -WIN) s1 += __expf(acc[mi][ni][2] - Mb);
                d = r1g - (t0 + 1); if (d < WIN && d > -WIN) s1 += __expf(acc[mi][ni][3] - Mb);
            }
            red[(rb + mi * 16) * 16 + slot]     = s0;
            red[(rb + mi * 16 + 8) * 16 + slot] = s1;
        }
        __syncthreads();
        if (tid < 128) {
            float l = 0.f;
            #pragma unroll
            for (int i = 0; i < 16; i++) l += red[tid * 16 + i];
            const int r = bm * 128 + tid;
            pm[(size_t)r * 32 + bn] = rowm[tid];
            pl[(size_t)r * 32 + bn] = l;
        }
    }
}

// ---------------- combine per-tile partials -> per-row (M, 1/L) -------------
__global__ __launch_bounds__(128)
void k_combine(const float* __restrict__ pm, const float* __restrict__ pl,
               float* __restrict__ rowM, float* __restrict__ rowI)
{
    const int r = blockIdx.x * 4 + (threadIdx.x >> 5);
    const int lane = threadIdx.x & 31;
    const int bm = r >> 7;
    const int blo = max(0, bm - 8), bhi = min(31, bm + 8);
    float m = -3.4e38f, lv = 0.f;
    const int bn = blo + lane;
    if (bn <= bhi) { m = pm[(size_t)r * 32 + bn]; lv = pl[(size_t)r * 32 + bn]; }
    const float mo = m;
    #pragma unroll
    for (int o = 16; o; o >>= 1) m = fmaxf(m, __shfl_xor_sync(~0u, m, o));
    float s = lv * __expf(mo - m);
    #pragma unroll
    for (int o = 16; o; o >>= 1) s += __shfl_xor_sync(~0u, s, o);
    if (lane == 0) { rowM[r] = m; rowI[r] = 1.f / s; }
}

// ---------------- fp32 -> fp16 copy (Wq only) --------------------------------
__global__ __launch_bounds__(256)
void k_tohalf(const float* __restrict__ in, __half* __restrict__ out, int n4)
{
    for (int i = blockIdx.x * 256 + threadIdx.x; i < n4; i += gridDim.x * 256) {
        float4 v = ((const float4*)in)[i];
        ((__half2*)out)[2 * i]     = __floats2half2_rn(v.x, v.y);
        ((__half2*)out)[2 * i + 1] = __floats2half2_rn(v.z, v.w);
    }
}

// ---------------- Pv [T][D] -> Pv^T [D][T] fp16 -----------------------------
__global__ __launch_bounds__(256)
void k_transpose_h(const float* __restrict__ in, __half* __restrict__ out)
{
    __shared__ float t[32][33];
    const int bx = blockIdx.x, by = blockIdx.y;
    const int tx = threadIdx.x, ty0 = threadIdx.y;
    #pragma unroll
    for (int i = 0; i < 4; i++) {
        int ty = ty0 + i * 8;
        t[ty][tx] = in[(size_t)(bx * 32 + ty) * DD + by * 32 + tx];
    }
    __syncthreads();
    #pragma unroll
    for (int i = 0; i < 4; i++) {
        int ty = ty0 + i * 8;
        out[(size_t)(by * 32 + ty) * TT + bx * 32 + tx] = __float2half_rn(t[tx][ty]);
    }
}

// ---------------------------------------------------------------------------
extern "C" void kernel_launch(void* const* d_in, const int* in_sizes, int n_in,
                              void* d_out, int out_size)
{
    const float* x  = (const float*)d_in[0];   // (L, d)
    const float* Wq = (const float*)d_in[1];   // (d, d)
    const float* Pk = (const float*)d_in[2];   // (1, T, d)
    const float* Pv = (const float*)d_in[3];   // (1, T, d)
    float* out = (float*)d_out;                // (1, L, d)

    __half *w16, *q16, *v16;
    float *S, *pm, *pl, *rM, *rI;
    cudaGetSymbolAddress((void**)&w16, g_w16);
    cudaGetSymbolAddress((void**)&q16, g_q16);
    cudaGetSymbolAddress((void**)&v16, g_v16);
    cudaGetSymbolAddress((void**)&S,   g_S);
    cudaGetSymbolAddress((void**)&pm,  g_pm);
    cudaGetSymbolAddress((void**)&pl,  g_pl);
    cudaGetSymbolAddress((void**)&rM,  g_rowM);
    cudaGetSymbolAddress((void**)&rI,  g_rowI);

    // G1: A32 (x fp32), B=w16, out fp16 Q*scale
    auto* G1 = h_gemm<false, false, true, false, false, true, false>;
    // G2: BAND, B32 (Pk fp32), out fp32 S + partials
    auto* G2 = h_gemm<true, false, false, true, false, false, true>;
    // G3: KRANGE, A32+EXPA (S fp32 -> softmax probs), B=v16, out fp32
    auto* G3 = h_gemm<false, true, true, false, true, false, false>;
    cudaFuncSetAttribute(G1, cudaFuncAttributeMaxDynamicSharedMemorySize, SMEM_B);
    cudaFuncSetAttribute(G2, cudaFuncAttributeMaxDynamicSharedMemorySize, SMEM_B);
    cudaFuncSetAttribute(G3, cudaFuncAttributeMaxDynamicSharedMemorySize, SMEM_B);

    const float scale = 1.0f / sqrtf((float)DD);

    k_tohalf<<<1024, 256>>>(Wq, w16, DD * DD / 4);
    k_transpose_h<<<dim3(TT / 32, DD / 32), dim3(32, 8)>>>(Pv, v16);

    G1<<<dim3(DD / 128, LQ / 128), 256, SMEM_B>>>(
        x, w16, nullptr, q16, nullptr, nullptr, nullptr, nullptr, DD, DD, scale);

    G2<<<dim3(TT / 128, LQ / 128), 256, SMEM_B>>>(
        q16, Pk, S, nullptr, pm, pl, nullptr, nullptr, TT, DD, 1.0f);

    k_combine<<<LQ / 4, 128>>>(pm, pl, rM, rI);

    G3<<<dim3(DD / 128, LQ / 128), 256, SMEM_B>>>(
        S, v16, out, nullptr, nullptr, nullptr, rM, rI, DD, TT, 1.0f);
}

// round 14
// speedup vs baseline: 1.3424x; 1.3424x over previous
#include <cuda_runtime.h>
#include <cuda_fp16.h>
#include <math.h>
#include <stdint.h>

#define LQ  4096
#define DD  2048
#define TT  4096
#define WIN 1024

// ---------------- scratch (device globals; no allocation APIs) --------------
__device__ alignas(16) __half g_x16[(size_t)LQ * DD];   // x       fp16
__device__ alignas(16) __half g_w16[(size_t)DD * DD];   // Wq      fp16
__device__ alignas(16) __half g_k16[(size_t)TT * DD];   // Pk      fp16
__device__ alignas(16) __half g_q16[(size_t)LQ * DD];   // Q*scale fp16
__device__ alignas(16) __half g_p16[(size_t)LQ * TT];   // probs   fp16
__device__ alignas(16) __half g_v16[(size_t)DD * TT];   // Pv^T    fp16
__device__ float g_S[(size_t)LQ * TT];                  // scores  fp32

// ---------------- PTX helpers ----------------------------------------------
__device__ __forceinline__ uint32_t smem_u32(const void* p) {
    uint32_t a;
    asm("{ .reg .u64 t; cvta.to.shared.u64 t, %1; cvt.u32.u64 %0, t; }"
        : "=r"(a) : "l"(p));
    return a;
}
#define CP_ASYNC16(dst, src) \
    asm volatile("cp.async.cg.shared.global [%0], [%1], 16;" :: "r"(dst), "l"(src))
#define CP_COMMIT() asm volatile("cp.async.commit_group;" ::: "memory")
#define CP_WAIT(n)  asm volatile("cp.async.wait_group %0;" :: "n"(n) : "memory")

#define LDSM4(r0, r1, r2, r3, addr) \
    asm volatile("ldmatrix.sync.aligned.m8n8.x4.shared.b16 {%0,%1,%2,%3}, [%4];" \
                 : "=r"(r0), "=r"(r1), "=r"(r2), "=r"(r3) : "r"(addr))

__device__ __forceinline__ void mma_f16(float* c, const uint32_t* a, const uint32_t* b) {
    asm volatile("mma.sync.aligned.m16n8k16.row.col.f32.f16.f16.f32 "
                 "{%0,%1,%2,%3}, {%4,%5,%6,%7}, {%8,%9}, {%0,%1,%2,%3};"
                 : "+f"(c[0]), "+f"(c[1]), "+f"(c[2]), "+f"(c[3])
                 : "r"(a[0]), "r"(a[1]), "r"(a[2]), "r"(a[3]),
                   "r"(b[0]), "r"(b[1]));
}

// ---------------- fp16 NT GEMM: C[M,N] = A[M,K] * B[N,K]^T ------------------
// 128x128 CTA tile, BK=32, cp.async double buffer, 256 thr, 8 warps of 64x32.
// Smem rows padded to stride 40 halves (80B) -> conflict-free ldmatrix.
static constexpr int HSTR   = 40;
static constexpr int TILE_H = 128 * HSTR;
static constexpr int BUF_H  = 2 * TILE_H;
static constexpr int SMEM_B = 2 * BUF_H * 2;      // 40960 bytes

template<bool BAND, bool KRANGE, bool OUTH>
__global__ __launch_bounds__(256, 2)
void h_gemm_nt(const __half* __restrict__ A, const __half* __restrict__ B,
               float* __restrict__ Cf, __half* __restrict__ Ch,
               int Ntot, int Ktot, float scale)
{
    const int bm = blockIdx.y, bn = blockIdx.x;
    if (BAND) {
        const int r0 = bm << 7, c0 = bn << 7;
        int dist = 0;
        if (c0 > r0 + 127)      dist = c0 - (r0 + 127);
        else if (r0 > c0 + 127) dist = r0 - (c0 + 127);
        if (dist >= WIN) return;
    }
    int k0 = 0, kend = Ktot;
    if (KRANGE) {
        k0 = bm * 128 - (WIN - 1); if (k0 < 0) k0 = 0; k0 &= ~31;
        kend = bm * 128 + 127 + WIN;
        kend = (kend + 31) & ~31; if (kend > Ktot) kend = Ktot;
    }
    const int nT = (kend - k0) >> 5;

    extern __shared__ __half sm[];
    const int tid = threadIdx.x, lane = tid & 31, w = tid >> 5;
    const int wm = (w & 1) * 64, wn = (w >> 1) * 32;

    const __half* Ag = A + (size_t)(bm * 128) * Ktot + k0;
    const __half* Bg = B + (size_t)(bn * 128) * Ktot + k0;

    const int srow = tid >> 2, sc = tid & 3;

    auto stage = [&](int t, int buf) {
        __half* As = sm + buf * BUF_H;
        __half* Bs = As + TILE_H;
        const int kb = t << 5;
        #pragma unroll
        for (int i = 0; i < 2; i++) {
            const int r = srow + i * 64;
            uint32_t da = smem_u32(As + r * HSTR + sc * 8);
            uint32_t db = smem_u32(Bs + r * HSTR + sc * 8);
            CP_ASYNC16(da, Ag + (size_t)r * Ktot + kb + sc * 8);
            CP_ASYNC16(db, Bg + (size_t)r * Ktot + kb + sc * 8);
        }
        CP_COMMIT();
    };

    float acc[4][4][4] = {};
    const int lr = lane & 7, ls = lane >> 3;

    stage(0, 0);

    for (int t = 0; t < nT; t++) {
        const int buf = t & 1;
        if (t + 1 < nT) { stage(t + 1, buf ^ 1); CP_WAIT(1); }
        else            { CP_WAIT(0); }
        __syncthreads();

        const __half* As = sm + buf * BUF_H;
        const __half* Bs = As + TILE_H;

        uint32_t bfr[4][4];
        #pragma unroll
        for (int ni = 0; ni < 4; ni++) {
            uint32_t ad = smem_u32(Bs + (wn + ni * 8 + lr) * HSTR + ls * 8);
            LDSM4(bfr[ni][0], bfr[ni][1], bfr[ni][2], bfr[ni][3], ad);
        }
        #pragma unroll
        for (int ks = 0; ks < 2; ks++) {
            uint32_t af[4][4];
            #pragma unroll
            for (int mi = 0; mi < 4; mi++) {
                uint32_t ad = smem_u32(As + (wm + mi * 16 + lr + (ls & 1) * 8) * HSTR
                                          + ks * 16 + (ls >> 1) * 8);
                LDSM4(af[mi][0], af[mi][1], af[mi][2], af[mi][3], ad);
            }
            #pragma unroll
            for (int mi = 0; mi < 4; mi++)
                #pragma unroll
                for (int ni = 0; ni < 4; ni++)
                    mma_f16(acc[mi][ni], af[mi], &bfr[ni][ks * 2]);
        }
        __syncthreads();
    }

    #pragma unroll
    for (int mi = 0; mi < 4; mi++) {
        const int row = bm * 128 + wm + mi * 16 + (lane >> 2);
        #pragma unroll
        for (int ni = 0; ni < 4; ni++) {
            const int col = bn * 128 + wn + ni * 8 + 2 * (lane & 3);
            if (OUTH) {
                __half2* p0 = (__half2*)(Ch + (size_t)row * Ntot + col);
                __half2* p1 = (__half2*)(Ch + (size_t)(row + 8) * Ntot + col);
                *p0 = __floats2half2_rn(acc[mi][ni][0] * scale, acc[mi][ni][1] * scale);
                *p1 = __floats2half2_rn(acc[mi][ni][2] * scale, acc[mi][ni][3] * scale);
            } else {
                float2* p0 = (float2*)(Cf + (size_t)row * Ntot + col);
                float2* p1 = (float2*)(Cf + (size_t)(row + 8) * Ntot + col);
                *p0 = make_float2(acc[mi][ni][0] * scale, acc[mi][ni][1] * scale);
                *p1 = make_float2(acc[mi][ni][2] * scale, acc[mi][ni][3] * scale);
            }
        }
    }
}

// ---------------- merged fp32 -> fp16 copy (x, Wq, Pk in one launch) --------
__global__ __launch_bounds__(256)
void k_tohalf3(const float* __restrict__ s0, __half* __restrict__ d0, int n0,
               const float* __restrict__ s1, __half* __restrict__ d1, int n1,
               const float* __restrict__ s2, __half* __restrict__ d2, int n2)
{
    const int total = n0 + n1 + n2;
    for (int i = blockIdx.x * 256 + threadIdx.x; i < total; i += gridDim.x * 256) {
        const float* in; __half* out; int j = i;
        if (j < n0)            { in = s0; out = d0; }
        else if ((j -= n0) < n1) { in = s1; out = d1; }
        else                   { j -= n1; in = s2; out = d2; }
        float4 v = ((const float4*)in)[j];
        ((__half2*)out)[2 * j]     = __floats2half2_rn(v.x, v.y);
        ((__half2*)out)[2 * j + 1] = __floats2half2_rn(v.z, v.w);
    }
}

// ---------------- Pv [T][D] -> Pv^T [D][T] fp16 -----------------------------
__global__ __launch_bounds__(256)
void k_transpose_h(const float* __restrict__ in, __half* __restrict__ out)
{
    __shared__ float t[32][33];
    const int bx = blockIdx.x, by = blockIdx.y;
    const int tx = threadIdx.x, ty0 = threadIdx.y;
    #pragma unroll
    for (int i = 0; i < 4; i++) {
        int ty = ty0 + i * 8;
        t[ty][tx] = in[(size_t)(bx * 32 + ty) * DD + by * 32 + tx];
    }
    __syncthreads();
    #pragma unroll
    for (int i = 0; i < 4; i++) {
        int ty = ty0 + i * 8;
        out[(size_t)(by * 32 + ty) * TT + bx * 32 + tx] = __float2half_rn(t[tx][ty]);
    }
}

// ---------------- banded softmax: fp32 scores -> fp16 probs ------------------
// Single gmem read of the band (cached in registers), shuffle reductions.
// Zeros written only inside the K-range union that GEMM3 will read.
__global__ __launch_bounds__(256)
void k_softmax(const float* __restrict__ S, __half* __restrict__ P)
{
    const int row = blockIdx.x;
    const int lo  = max(0, row - (WIN - 1));
    const int hi  = min(TT - 1, row + (WIN - 1));
    const int bm  = row >> 7;
    int k0u = bm * 128 - (WIN - 1); if (k0u < 0) k0u = 0; k0u &= ~31;
    int keu = bm * 128 + 127 + WIN; keu = (keu + 31) & ~31; if (keu > TT) keu = TT;

    const float* sr = S + (size_t)row * TT;
    __half* pr = P + (size_t)row * TT;

    const int tid = threadIdx.x, lane = tid & 31, wid = tid >> 5;
    __shared__ float sred[8];

    // single pass read: cache band values in registers
    float v[8];
    int nv = 0;
    float mx = -3.402823e38f;
    for (int t = lo + tid; t <= hi; t += 256, nv++) {
        v[nv] = sr[t];
        mx = fmaxf(mx, v[nv]);
    }
    #pragma unroll
    for (int o = 16; o; o >>= 1) mx = fmaxf(mx, __shfl_xor_sync(~0u, mx, o));
    if (lane == 0) sred[wid] = mx;
    __syncthreads();
    #pragma unroll
    for (int i = 0; i < 8; i++) mx = fmaxf(mx, sred[i]);
    __syncthreads();

    float sum = 0.0f;
    #pragma unroll
    for (int j = 0; j < 8; j++)
        if (j < nv) { v[j] = __expf(v[j] - mx); sum += v[j]; }
    #pragma unroll
    for (int o = 16; o; o >>= 1) sum += __shfl_xor_sync(~0u, sum, o);
    if (lane == 0) sred[wid] = sum;
    __syncthreads();
    sum = 0.0f;
    #pragma unroll
    for (int i = 0; i < 8; i++) sum += sred[i];
    const float inv = 1.0f / sum;

    const __half z = __float2half_rn(0.0f);
    for (int t = k0u + tid; t < lo; t += 256)     pr[t] = z;
    for (int t = hi + 1 + tid; t < keu; t += 256) pr[t] = z;
    {
        int j = 0;
        for (int t = lo + tid; t <= hi; t += 256, j++)
            pr[t] = __float2half_rn(v[j] * inv);
    }
}

// ---------------------------------------------------------------------------
extern "C" void kernel_launch(void* const* d_in, const int* in_sizes, int n_in,
                              void* d_out, int out_size)
{
    const float* x  = (const float*)d_in[0];   // (L, d)
    const float* Wq = (const float*)d_in[1];   // (d, d)
    const float* Pk = (const float*)d_in[2];   // (1, T, d)
    const float* Pv = (const float*)d_in[3];   // (1, T, d)
    float* out = (float*)d_out;                // (1, L, d)

    __half *x16, *w16, *k16, *q16, *p16, *v16;
    float* S;
    cudaGetSymbolAddress((void**)&x16, g_x16);
    cudaGetSymbolAddress((void**)&w16, g_w16);
    cudaGetSymbolAddress((void**)&k16, g_k16);
    cudaGetSymbolAddress((void**)&q16, g_q16);
    cudaGetSymbolAddress((void**)&p16, g_p16);
    cudaGetSymbolAddress((void**)&v16, g_v16);
    cudaGetSymbolAddress((void**)&S,   g_S);

    cudaFuncSetAttribute(h_gemm_nt<false, false, true>,
                         cudaFuncAttributeMaxDynamicSharedMemorySize, SMEM_B);
    cudaFuncSetAttribute(h_gemm_nt<true, false, false>,
                         cudaFuncAttributeMaxDynamicSharedMemorySize, SMEM_B);
    cudaFuncSetAttribute(h_gemm_nt<false, true, false>,
                         cudaFuncAttributeMaxDynamicSharedMemorySize, SMEM_B);

    const float scale = 1.0f / sqrtf((float)DD);

    // 0) operand conversions (one merged launch + transpose)
    k_tohalf3<<<2048, 256>>>(x,  x16, LQ * DD / 4,
                             Wq, w16, DD * DD / 4,
                             Pk, k16, TT * DD / 4);
    k_transpose_h<<<dim3(TT / 32, DD / 32), dim3(32, 8)>>>(Pv, v16);

    // 1) Q = (x @ Wq^T) * scale  -> fp16
    h_gemm_nt<false, false, true><<<dim3(DD / 128, LQ / 128), 256, SMEM_B>>>(
        x16, w16, nullptr, q16, DD, DD, scale);

    // 2) S = Q @ Pk^T (band tiles only) -> fp32
    h_gemm_nt<true, false, false><<<dim3(TT / 128, LQ / 128), 256, SMEM_B>>>(
        q16, k16, S, nullptr, TT, DD, 1.0f);

    // 3) banded softmax -> fp16 probs (zeros inside G3 K-range union)
    k_softmax<<<LQ, 256>>>(S, p16);

    // 4) y = P @ PvT^T, K restricted to band union per row-block -> fp32 out
    h_gemm_nt<false, true, false><<<dim3(DD / 128, LQ / 128), 256, SMEM_B>>>(
        p16, v16, out, nullptr, DD, TT, 1.0f);
}